// round 17
// baseline (speedup 1.0000x reference)
#include <cuda_runtime.h>
#include <cuda_bf16.h>
#include <math.h>
#include <string.h>
#include <stdint.h>

#define C 256
#define BATCH 8
#define NTOK 5376
#define TOT (BATCH*NTOK)   /* 43008 */
#define KINST 100
#define LN_EPS 1e-5f

#define NI_OFF 0
#define SC_OFF 8
#define CL_OFF 808
#define BX_OFF 1608

// ---------------- device scratch ----------------
__device__ __nv_bfloat16 g_flathi[TOT*C], g_flatlo[TOT*C];
__device__ __nv_bfloat16 g_p0hi[TOT*C],  g_p0lo[TOT*C];
__device__ __nv_bfloat16 g_p1hi[TOT*C],  g_p1lo[TOT*C];
__device__ float g_logits[TOT];
__device__ float g_vals[BATCH*KINST];
__device__ int   g_idx[BATCH*KINST];
__device__ __nv_bfloat16 g_hd[4][896*256];
__device__ __nv_bfloat16 g_whi[12*65536];
__device__ __nv_bfloat16 g_wlo[12*65536];
__device__ __nv_bfloat16 g_lathi[458752];
__device__ __nv_bfloat16 g_latlo[458752];

// ---------------- helpers ----------------
__device__ __forceinline__ uint32_t smem_u32(const void* p){
    uint32_t a;
    asm("{ .reg .u64 t; cvta.to.shared.u64 t, %1; cvt.u32.u64 %0, t; }" : "=r"(a) : "l"(p));
    return a;
}
__device__ __forceinline__ uint32_t sw128(uint32_t o){ return o ^ ((o >> 3) & 0x70); }
__device__ __forceinline__ uint32_t sw64(uint32_t o){ return o ^ ((o >> 3) & 0x30); }

__device__ __forceinline__ void ldsm4(uint32_t addr, uint32_t& r0, uint32_t& r1,
                                      uint32_t& r2, uint32_t& r3){
    asm volatile("ldmatrix.sync.aligned.m8n8.x4.shared.b16 {%0,%1,%2,%3}, [%4];"
                 : "=r"(r0), "=r"(r1), "=r"(r2), "=r"(r3) : "r"(addr));
}
__device__ __forceinline__ void mma_bf16(float* d, const uint32_t* a, uint32_t b0, uint32_t b1){
    asm volatile(
        "mma.sync.aligned.m16n8k16.row.col.f32.bf16.bf16.f32 "
        "{%0,%1,%2,%3}, {%4,%5,%6,%7}, {%8,%9}, {%0,%1,%2,%3};"
        : "+f"(d[0]), "+f"(d[1]), "+f"(d[2]), "+f"(d[3])
        : "r"(a[0]), "r"(a[1]), "r"(a[2]), "r"(a[3]), "r"(b0), "r"(b1));
}
__device__ __forceinline__ void cpasync16(uint32_t dst, const void* src){
    asm volatile("cp.async.cg.shared.global [%0], [%1], 16;" :: "r"(dst), "l"(src));
}
__device__ __forceinline__ void cp_commit(){
    asm volatile("cp.async.commit_group;" ::: "memory");
}
__device__ __forceinline__ void cp_wait1(){
    asm volatile("cp.async.wait_group 1;" ::: "memory");
}
__device__ __forceinline__ void store_hl2(__nv_bfloat16* Yhi, __nv_bfloat16* Ylo,
                                          size_t row, int c0, float u0, float u1){
    __nv_bfloat16 h0=__float2bfloat16(u0), h1=__float2bfloat16(u1);
    __nv_bfloat16 l0=__float2bfloat16(u0-__bfloat162float(h0));
    __nv_bfloat16 l1=__float2bfloat16(u1-__bfloat162float(h1));
    __nv_bfloat162 hh; hh.x=h0; hh.y=h1;
    __nv_bfloat162 ll; ll.x=l0; ll.y=l1;
    *(__nv_bfloat162*)(Yhi+row*256+c0) = hh;
    *(__nv_bfloat162*)(Ylo+row*256+c0) = ll;
}

// ---------------- K=32 double-buffered smem layout (3 CTAs/SM) ----------------
// A stage: hi 2KB (32 rows x 64B, SW64) + lo 2KB. B stage: Bh 16KB + Bl 16KB.
#define A_ST(s)  ((uint32_t)(s) * 4096u)
#define A_LO     2048u
#define B_ST(s)  (8192u + (uint32_t)(s) * 32768u)
#define B_LO     16384u
#define P_RS    73728
#define P_RQ    73856
#define P_RD    73984
#define P_SIDX  74112
#define SMEM_TOTAL 74240

// merged 3-pass compute for one K=32 chunk. abuf: A-hi base; bbuf: Bh base.
__device__ __forceinline__ void chunk32k(uint32_t abuf, uint32_t bbuf, int lane, int wn,
                                         float acc[2][4][4]){
    const int lm_r = (lane & 7) + ((lane >> 3) & 1) * 8;
    const int lm_k = (lane >> 4) * 16;
#pragma unroll
    for (int ks = 0; ks < 2; ks++) {
        const int kb = ks * 32 + lm_k;
        uint32_t ah[2][4], bh[2][4];
#pragma unroll
        for (int mi = 0; mi < 2; mi++) {
            int row = mi * 16 + lm_r;
            ldsm4(abuf + sw64((uint32_t)(row * 64 + kb)),
                  ah[mi][0], ah[mi][1], ah[mi][2], ah[mi][3]);
        }
#pragma unroll
        for (int t = 0; t < 2; t++) {
            int nr = wn * 32 + t * 16 + lm_r;
            ldsm4(bbuf + sw64((uint32_t)(nr * 64 + kb)),
                  bh[t][0], bh[t][1], bh[t][2], bh[t][3]);
        }
        // pass 1: Ah x Bh (8 distinct accumulators)
#pragma unroll
        for (int t = 0; t < 2; t++)
#pragma unroll
            for (int mi = 0; mi < 2; mi++) {
                mma_bf16(acc[mi][t*2],   ah[mi], bh[t][0], bh[t][2]);
                mma_bf16(acc[mi][t*2+1], ah[mi], bh[t][1], bh[t][3]);
            }
        // pass 3: Al x Bh
        uint32_t al[2][4];
#pragma unroll
        for (int mi = 0; mi < 2; mi++) {
            int row = mi * 16 + lm_r;
            ldsm4(abuf + A_LO + sw64((uint32_t)(row * 64 + kb)),
                  al[mi][0], al[mi][1], al[mi][2], al[mi][3]);
        }
#pragma unroll
        for (int t = 0; t < 2; t++)
#pragma unroll
            for (int mi = 0; mi < 2; mi++) {
                mma_bf16(acc[mi][t*2],   al[mi], bh[t][0], bh[t][2]);
                mma_bf16(acc[mi][t*2+1], al[mi], bh[t][1], bh[t][3]);
            }
        // pass 2: Ah x Bl
        uint32_t bl[2][4];
#pragma unroll
        for (int t = 0; t < 2; t++) {
            int nr = wn * 32 + t * 16 + lm_r;
            ldsm4(bbuf + B_LO + sw64((uint32_t)(nr * 64 + kb)),
                  bl[t][0], bl[t][1], bl[t][2], bl[t][3]);
        }
#pragma unroll
        for (int t = 0; t < 2; t++)
#pragma unroll
            for (int mi = 0; mi < 2; mi++) {
                mma_bf16(acc[mi][t*2],   ah[mi], bl[t][0], bl[t][2]);
                mma_bf16(acc[mi][t*2+1], ah[mi], bl[t][1], bl[t][3]);
            }
    }
}

struct GArgs {
    const __nv_bfloat16 *Ahi, *Alo;
    const __nv_bfloat16 *Whi, *Wlo;
    const float *pb, *pg, *po;
    __nv_bfloat16 *Yhi, *Ylo;
    const float *wf, *wfb;
    float* logits;
    int nrows;
};

// ============================================================================
// tc_gemm (256 threads, 8 warps, 3 CTAs/SM): D[32-row tile, 256] = X @ W.
// K=256 in 8 chunks of 32, fully double-buffered (loads always hidden).
// ============================================================================
__global__ __launch_bounds__(256, 3) void tc_gemm(GArgs a)
{
    extern __shared__ char smem[];
    const uint32_t sbase = smem_u32(smem);
    const int tid  = threadIdx.x;
    const int lane = tid & 31;
    const int wn   = tid >> 5;
    const int row0 = blockIdx.x * 32;

    if (tid < 32) {
        ((float*)(smem+P_RS))[tid] = 0.f;
        ((float*)(smem+P_RQ))[tid] = 0.f;
        ((float*)(smem+P_RD))[tid] = 0.f;
        int i = row0 + tid; if (i >= a.nrows) i = a.nrows - 1;
        ((int*)(smem+P_SIDX))[tid] = i;
    }
    __syncthreads();

    const int* sidx = (const int*)(smem + P_SIDX);

    // hoisted load addressing
    const int t7 = tid & 127;
    const int ar = t7 >> 2, as4 = t7 & 3;
    const uint32_t adst = sbase + (tid < 128 ? 0u : A_LO)
                        + sw64((uint32_t)(ar * 64 + as4 * 16));
    const __nv_bfloat16* abase = (tid < 128 ? a.Ahi : a.Alo)
                               + (size_t)sidx[ar] * 256 + as4 * 8;
    const int bo = tid >> 2, bs4 = tid & 3;
    const uint32_t bdst = sbase + sw64((uint32_t)(bo * 64 + bs4 * 16));
    const __nv_bfloat16* bsrch = a.Whi + (size_t)bo * 256 + bs4 * 8;
    const __nv_bfloat16* bsrcl = a.Wlo + (size_t)bo * 256 + bs4 * 8;

    float acc[2][4][4];
#pragma unroll
    for (int mi = 0; mi < 2; mi++)
#pragma unroll
        for (int ni = 0; ni < 4; ni++)
#pragma unroll
            for (int q = 0; q < 4; q++) acc[mi][ni][q] = 0.f;

    auto issueAB = [&](int kc){
        const uint32_t ast = A_ST(kc & 1), bst = B_ST(kc & 1);
        cpasync16(adst + ast, abase + kc * 32);
#pragma unroll
        for (int j = 0; j < 4; j++) {
            cpasync16(bdst + bst + (uint32_t)(j * 4096),        bsrch + kc * 32 + j * 16384);
            cpasync16(bdst + bst + B_LO + (uint32_t)(j * 4096), bsrcl + kc * 32 + j * 16384);
        }
    };

    issueAB(0); cp_commit();
    issueAB(1); cp_commit();

#pragma unroll 1
    for (int kc = 0; kc < 8; kc++) {
        cp_wait1();
        __syncthreads();
        chunk32k(sbase + A_ST(kc & 1), sbase + B_ST(kc & 1), lane, wn, acc);
        __syncthreads();
        if (kc + 2 < 8) issueAB(kc + 2);
        cp_commit();
    }

    // ---- epilogue ----
    float* rowsum = (float*)(smem + P_RS);
    float* rowsq  = (float*)(smem + P_RQ);
    float* rowdot = (float*)(smem + P_RD);
    const int rloc = lane >> 2;

#pragma unroll
    for (int mi = 0; mi < 2; mi++) {
        float sA=0.f, qA=0.f, sB=0.f, qB=0.f;
#pragma unroll
        for (int ni = 0; ni < 4; ni++) {
            int c0 = wn * 32 + ni * 8 + (lane & 3) * 2;
            float b0 = __ldg(a.pb + c0), b1 = __ldg(a.pb + c0 + 1);
            float v0 = acc[mi][ni][0] + b0;
            float v1 = acc[mi][ni][1] + b1;
            float v2 = acc[mi][ni][2] + b0;
            float v3 = acc[mi][ni][3] + b1;
            acc[mi][ni][0]=v0; acc[mi][ni][1]=v1; acc[mi][ni][2]=v2; acc[mi][ni][3]=v3;
            sA += v0 + v1; qA += v0*v0 + v1*v1;
            sB += v2 + v3; qB += v2*v2 + v3*v3;
        }
#pragma unroll
        for (int o = 1; o <= 2; o <<= 1) {
            sA += __shfl_xor_sync(0xffffffffu, sA, o);
            qA += __shfl_xor_sync(0xffffffffu, qA, o);
            sB += __shfl_xor_sync(0xffffffffu, sB, o);
            qB += __shfl_xor_sync(0xffffffffu, qB, o);
        }
        if ((lane & 3) == 0) {
            int rA = mi * 16 + rloc;
            atomicAdd(&rowsum[rA], sA);   atomicAdd(&rowsq[rA], qA);
            atomicAdd(&rowsum[rA+8], sB); atomicAdd(&rowsq[rA+8], qB);
        }
    }
    __syncthreads();

    if (a.wf) {
#pragma unroll
        for (int mi = 0; mi < 2; mi++) {
            int rA = mi * 16 + rloc;
            int rB = rA + 8;
            float mA = rowsum[rA] * (1.f/256.f);
            float rsA = rsqrtf(rowsq[rA] * (1.f/256.f) - mA*mA + LN_EPS);
            float mB = rowsum[rB] * (1.f/256.f);
            float rsB = rsqrtf(rowsq[rB] * (1.f/256.f) - mB*mB + LN_EPS);
            float pA = 0.f, pB = 0.f;
#pragma unroll
            for (int ni = 0; ni < 4; ni++) {
                int c0 = wn * 32 + ni * 8 + (lane & 3) * 2;
                float g0=__ldg(a.pg+c0), g1=__ldg(a.pg+c0+1);
                float o0=__ldg(a.po+c0), o1=__ldg(a.po+c0+1);
                float w0=__ldg(a.wf+c0), w1=__ldg(a.wf+c0+1);
                float u0 = (acc[mi][ni][0]-mA)*rsA*g0 + o0;
                float u1 = (acc[mi][ni][1]-mA)*rsA*g1 + o1;
                float u2 = (acc[mi][ni][2]-mB)*rsB*g0 + o0;
                float u3 = (acc[mi][ni][3]-mB)*rsB*g1 + o1;
                u0 = u0/(1.f+expf(-u0)); u1 = u1/(1.f+expf(-u1));
                u2 = u2/(1.f+expf(-u2)); u3 = u3/(1.f+expf(-u3));
                pA += u0*w0 + u1*w1;
                pB += u2*w0 + u3*w1;
            }
#pragma unroll
            for (int o = 1; o <= 2; o <<= 1) {
                pA += __shfl_xor_sync(0xffffffffu, pA, o);
                pB += __shfl_xor_sync(0xffffffffu, pB, o);
            }
            if ((lane & 3) == 0) {
                atomicAdd(&rowdot[rA], pA);
                atomicAdd(&rowdot[rB], pB);
            }
        }
        __syncthreads();
        if (tid < 32) {
            int rg = row0 + tid;
            if (rg < a.nrows) a.logits[rg] = rowdot[tid] + __ldg(a.wfb);
        }
    } else {
#pragma unroll
        for (int mi = 0; mi < 2; mi++) {
            int rA = mi * 16 + rloc;
            int rB = rA + 8;
            float mA = rowsum[rA] * (1.f/256.f);
            float rsA = rsqrtf(rowsq[rA] * (1.f/256.f) - mA*mA + LN_EPS);
            float mB = rowsum[rB] * (1.f/256.f);
            float rsB = rsqrtf(rowsq[rB] * (1.f/256.f) - mB*mB + LN_EPS);
            int rgA = row0 + rA, rgB = row0 + rB;
#pragma unroll
            for (int ni = 0; ni < 4; ni++) {
                int c0 = wn * 32 + ni * 8 + (lane & 3) * 2;
                float g0=__ldg(a.pg+c0), g1=__ldg(a.pg+c0+1);
                float o0=__ldg(a.po+c0), o1=__ldg(a.po+c0+1);
                float u0 = (acc[mi][ni][0]-mA)*rsA*g0 + o0;
                float u1 = (acc[mi][ni][1]-mA)*rsA*g1 + o1;
                float u2 = (acc[mi][ni][2]-mB)*rsB*g0 + o0;
                float u3 = (acc[mi][ni][3]-mB)*rsB*g1 + o1;
                u0 = u0/(1.f+expf(-u0)); u1 = u1/(1.f+expf(-u1));
                u2 = u2/(1.f+expf(-u2)); u3 = u3/(1.f+expf(-u3));
                if (rgA < a.nrows) store_hl2(a.Yhi, a.Ylo, (size_t)rgA, c0, u0, u1);
                if (rgB < a.nrows) store_hl2(a.Yhi, a.Ylo, (size_t)rgB, c0, u2, u3);
            }
        }
    }
}

// ============================================================================
// lat_gemm: 1344 CTAs (M=32, 3 CTAs/SM), K=32 chunks double-buffered;
// A fp32 register-prefetched one chunk ahead; biggest-work levels first.
// ============================================================================
struct LatArgs {
    const float *x3, *x4, *x5;
    const __nv_bfloat16 *Whi, *Wlo;
    const float *bn_g, *bn_b, *bn_m, *bn_v;
    __nv_bfloat16 *Yhi, *Ylo;
};

__global__ __launch_bounds__(256, 3) void lat_gemm(LatArgs a)
{
    extern __shared__ char smem[];
    const uint32_t sbase = smem_u32(smem);
    const int tid = threadIdx.x, lane = tid & 31, wn = tid >> 5;

    int blk = blockIdx.x;
    const float* Xf; int Kdim, HW, lvl_off, wofs, lv;
    if (blk < 64)       { lv=2; Xf=a.x5; Kdim=1024; HW=256;  lvl_off=5120; wofs=196608; }
    else if (blk < 320) { lv=1; blk-=64;  Xf=a.x4; Kdim=512;  HW=1024; lvl_off=4096; wofs=65536; }
    else                { lv=0; blk-=320; Xf=a.x3; Kdim=256;  HW=4096; lvl_off=0;    wofs=0; }
    const int row0 = blk * 32;
    const int bb = row0 / HW, hw0 = row0 % HW;
    const float* pg_bn = a.bn_g + lv*C;
    const float* pv_bn = a.bn_v + lv*C;
    const float* pb_bn = a.bn_b + lv*C;
    const float* pm_bn = a.bn_m + lv*C;

    // hoisted load addressing
    const int kk = tid >> 3, r4 = (tid & 7) * 4;
    const int bo = tid >> 2, bs4 = tid & 3;
    const uint32_t bdst = sbase + sw64((uint32_t)(bo * 64 + bs4 * 16));
    const __nv_bfloat16* bsrch = a.Whi + wofs + (size_t)bo * Kdim + bs4 * 8;
    const __nv_bfloat16* bsrcl = a.Wlo + wofs + (size_t)bo * Kdim + bs4 * 8;
    const size_t jstep = (size_t)64 * Kdim;

    float acc[2][4][4];
#pragma unroll
    for (int mi = 0; mi < 2; mi++)
#pragma unroll
        for (int ni = 0; ni < 4; ni++)
#pragma unroll
            for (int q = 0; q < 4; q++) acc[mi][ni][q] = 0.f;

    float4 areg;
    auto loadA = [&](int kc){
        areg = *(const float4*)(Xf + ((size_t)(bb * Kdim + kc * 32 + kk)) * HW + hw0 + r4);
    };
    auto convA = [&](uint32_t ast){
        float xs[4] = { areg.x, areg.y, areg.z, areg.w };
#pragma unroll
        for (int t = 0; t < 4; t++) {
            __nv_bfloat16 h = __float2bfloat16(xs[t]);
            __nv_bfloat16 l = __float2bfloat16(xs[t] - __bfloat162float(h));
            uint32_t so = sw64((uint32_t)((r4 + t) * 64 + kk * 2));
            *(unsigned short*)(smem + ast + so)        = __bfloat16_as_ushort(h);
            *(unsigned short*)(smem + ast + A_LO + so) = __bfloat16_as_ushort(l);
        }
    };
    auto issueB = [&](int kc){
        const uint32_t bst = B_ST(kc & 1);
#pragma unroll
        for (int j = 0; j < 4; j++) {
            cpasync16(bdst + bst + (uint32_t)(j * 4096),        bsrch + kc * 32 + j * jstep);
            cpasync16(bdst + bst + B_LO + (uint32_t)(j * 4096), bsrcl + kc * 32 + j * jstep);
        }
    };

    const int nch = Kdim >> 5;

    // prologue: A(0),A(1) converted; B(0),B(1) in flight
    loadA(0);
    issueB(0); cp_commit();
    convA(A_ST(0));
    loadA(1);
    issueB(1); cp_commit();
    convA(A_ST(1));

#pragma unroll 1
    for (int kc = 0; kc < nch; kc++) {
        cp_wait1();
        __syncthreads();                 // B[kc] + A STS visible
        if (kc + 2 < nch) loadA(kc + 2); // global LDG flies under compute
        chunk32k(sbase + A_ST(kc & 1), sbase + B_ST(kc & 1), lane, wn, acc);
        __syncthreads();                 // stage kc&1 dead
        if (kc + 2 < nch) { convA(A_ST(kc & 1)); issueB(kc + 2); }
        cp_commit();
    }

    const int rloc = lane >> 2;
#pragma unroll
    for (int mi = 0; mi < 2; mi++) {
        int rA = mi * 16 + rloc;
        int rB = rA + 8;
        size_t oA = (size_t)bb * NTOK + lvl_off + hw0 + rA;
        size_t oB = oA + 8;
#pragma unroll
        for (int ni = 0; ni < 4; ni++) {
            int c0 = wn * 32 + ni * 8 + (lane & 3) * 2;
            float g0 = __ldg(pg_bn+c0) * rsqrtf(__ldg(pv_bn+c0) + LN_EPS);
            float g1 = __ldg(pg_bn+c0+1) * rsqrtf(__ldg(pv_bn+c0+1) + LN_EPS);
            float o0f = __ldg(pb_bn+c0)   - __ldg(pm_bn+c0)   * g0;
            float o1f = __ldg(pb_bn+c0+1) - __ldg(pm_bn+c0+1) * g1;
            store_hl2(a.Yhi, a.Ylo, oA, c0, acc[mi][ni][0]*g0+o0f, acc[mi][ni][1]*g1+o1f);
            store_hl2(a.Yhi, a.Ylo, oB, c0, acc[mi][ni][2]*g0+o0f, acc[mi][ni][3]*g1+o1f);
        }
    }
}

// ============================================================================
// fused_heads (unchanged from R15): 50 CTAs, 128B-row layout, pass-split.
// ============================================================================
#define HF_A    0
#define HF_BH   32768
#define HF_BL   65536
#define HF_RS   98304
#define HF_RQ   98432
#define HF_SIDX 98560
#define HF_SMEM 98688

__device__ __forceinline__ void passes13(uint32_t aoff, uint32_t boff, int lane, int wn,
                                         float acc[2][4][4]){
    const int lm_r = (lane & 7) + ((lane >> 3) & 1) * 8;
    const int lm_k = (lane >> 4) * 16;
#pragma unroll
    for (int ks = 0; ks < 4; ks++) {
        const int kb = ks * 32 + lm_k;
        uint32_t ah[2][4], al[2][4];
#pragma unroll
        for (int mi = 0; mi < 2; mi++) {
            int row = mi * 16 + lm_r;
            uint32_t so = sw128((uint32_t)(row * 128 + kb));
            ldsm4(aoff + so,        ah[mi][0], ah[mi][1], ah[mi][2], ah[mi][3]);
            ldsm4(aoff + 4096 + so, al[mi][0], al[mi][1], al[mi][2], al[mi][3]);
        }
        uint32_t bh[2][4];
#pragma unroll
        for (int t = 0; t < 2; t++) {
            int nr = wn * 32 + t * 16 + lm_r;
            uint32_t so = sw128((uint32_t)(nr * 128 + kb));
            ldsm4(boff + so, bh[t][0], bh[t][1], bh[t][2], bh[t][3]);
        }
#pragma unroll
        for (int t = 0; t < 2; t++)
#pragma unroll
            for (int mi = 0; mi < 2; mi++) {
                mma_bf16(acc[mi][t*2],   ah[mi], bh[t][0], bh[t][2]);
                mma_bf16(acc[mi][t*2+1], ah[mi], bh[t][1], bh[t][3]);
            }
#pragma unroll
        for (int t = 0; t < 2; t++)
#pragma unroll
            for (int mi = 0; mi < 2; mi++) {
                mma_bf16(acc[mi][t*2],   al[mi], bh[t][0], bh[t][2]);
                mma_bf16(acc[mi][t*2+1], al[mi], bh[t][1], bh[t][3]);
            }
    }
}
__device__ __forceinline__ void pass2(uint32_t aoff, uint32_t boff, int lane, int wn,
                                      float acc[2][4][4]){
    const int lm_r = (lane & 7) + ((lane >> 3) & 1) * 8;
    const int lm_k = (lane >> 4) * 16;
#pragma unroll
    for (int ks = 0; ks < 4; ks++) {
        const int kb = ks * 32 + lm_k;
        uint32_t ah[2][4];
#pragma unroll
        for (int mi = 0; mi < 2; mi++) {
            int row = mi * 16 + lm_r;
            uint32_t so = sw128((uint32_t)(row * 128 + kb));
            ldsm4(aoff + so, ah[mi][0], ah[mi][1], ah[mi][2], ah[mi][3]);
        }
        uint32_t bl[2][4];
#pragma unroll
        for (int t = 0; t < 2; t++) {
            int nr = wn * 32 + t * 16 + lm_r;
            uint32_t so = sw128((uint32_t)(nr * 128 + kb));
            ldsm4(boff + 32768 + so, bl[t][0], bl[t][1], bl[t][2], bl[t][3]);
        }
#pragma unroll
        for (int t = 0; t < 2; t++)
#pragma unroll
            for (int mi = 0; mi < 2; mi++) {
                mma_bf16(acc[mi][t*2],   ah[mi], bl[t][0], bl[t][2]);
                mma_bf16(acc[mi][t*2+1], ah[mi], bl[t][1], bl[t][3]);
            }
    }
}

struct HArgs {
    const __nv_bfloat16 *Ahi, *Alo;
    const __nv_bfloat16 *whi, *wlo;
    const float *pb, *pg, *po;
    const float *pb2, *pg2, *po2;
    __nv_bfloat16 *Yhi, *Ylo, *Y2hi, *Y2lo;
    const int* idx;
};

__global__ __launch_bounds__(256) void fused_heads(HArgs a)
{
    extern __shared__ char smem[];
    const uint32_t sbase = smem_u32(smem);
    const int tid = threadIdx.x, lane = tid & 31, wn = tid >> 5;

    int blk = blockIdx.x;
    int mat0 = 4;
    const float *pb = a.pb, *pg = a.pg, *po = a.po;
    __nv_bfloat16 *Yhi = a.Yhi, *Ylo = a.Ylo;
    if (blk >= 25) {
        blk -= 25; mat0 = 8;
        pb = a.pb2; pg = a.pg2; po = a.po2; Yhi = a.Y2hi; Ylo = a.Y2lo;
    }
    const int row0 = blk * 32;

    if (tid < 32) {
        ((float*)(smem+HF_RS))[tid] = 0.f;
        ((float*)(smem+HF_RQ))[tid] = 0.f;
        int i = row0 + tid;
        ((int*)(smem+HF_SIDX))[tid] = (i / KINST) * NTOK + a.idx[i];
    }
    __syncthreads();

    const int o0 = tid >> 3, s8 = tid & 7;
    const uint32_t swp   = sw128((uint32_t)(o0 * 128 + s8 * 16));
    const uint32_t adsth = sbase + HF_A + swp;
    const uint32_t bdst0 = sbase + HF_BH + swp;
    const int* sidx = (const int*)(smem + HF_SIDX);
    const __nv_bfloat16* asrch = a.Ahi + (size_t)sidx[o0] * 256 + s8 * 8;
    const __nv_bfloat16* asrcl = a.Alo + (asrch - a.Ahi);

    float acc[2][4][4];
#pragma unroll
    for (int mi = 0; mi < 2; mi++)
#pragma unroll
        for (int ni = 0; ni < 4; ni++)
#pragma unroll
            for (int q = 0; q < 4; q++) acc[mi][ni][q] = 0.f;

#pragma unroll
    for (int kc = 0; kc < 4; kc++) {
        cpasync16(adsth + kc * 8192,        asrch + kc * 64);
        cpasync16(adsth + kc * 8192 + 4096, asrcl + kc * 64);
    }
    cp_commit();

    auto issueBh = [&](int g){
        const __nv_bfloat16* s = a.whi + (size_t)(mat0 + (g >> 2)) * 65536
                               + (size_t)o0 * 256 + s8 * 8 + (g & 3) * 64;
#pragma unroll
        for (int j = 0; j < 8; j++)
            cpasync16(bdst0 + j * 4096, s + j * 8192);
    };
    auto issueBl = [&](int g){
        const __nv_bfloat16* s = a.wlo + (size_t)(mat0 + (g >> 2)) * 65536
                               + (size_t)o0 * 256 + s8 * 8 + (g & 3) * 64;
#pragma unroll
        for (int j = 0; j < 8; j++)
            cpasync16(bdst0 + 32768 + j * 4096, s + j * 8192);
    };

    issueBh(0); cp_commit();
    issueBl(0); cp_commit();

    float* rowsum = (float*)(smem + HF_RS);
    float* rowsq  = (float*)(smem + HF_RQ);
    const int rloc = lane >> 2;

    for (int g = 0; g < 16; g++) {
        const int kc = g & 3, l = g >> 2;
        const uint32_t aoff = sbase + HF_A + (uint32_t)(kc * 8192);
        cp_wait1();
        __syncthreads();
        passes13(aoff, sbase + HF_BH, lane, wn, acc);
        __syncthreads();
        if (g < 15) issueBh(g + 1);
        cp_commit();
        cp_wait1();
        __syncthreads();
        pass2(aoff, sbase + HF_BH, lane, wn, acc);
        __syncthreads();
        if (g < 15) issueBl(g + 1);
        cp_commit();

        if (kc == 3) {
            const float* lpb = pb + l * 256;
            const float* lpg = pg + l * 256;
            const float* lpo = po + l * 256;
#pragma unroll
            for (int mi = 0; mi < 2; mi++) {
                float sA=0.f, qA=0.f, sB=0.f, qB=0.f;
#pragma unroll
                for (int ni = 0; ni < 4; ni++) {
                    int c0 = wn * 32 + ni * 8 + (lane & 3) * 2;
                    float b0 = __ldg(lpb + c0), b1 = __ldg(lpb + c0 + 1);
                    float v0 = acc[mi][ni][0] + b0;
                    float v1 = acc[mi][ni][1] + b1;
                    float v2 = acc[mi][ni][2] + b0;
                    float v3 = acc[mi][ni][3] + b1;
                    acc[mi][ni][0]=v0; acc[mi][ni][1]=v1;
                    acc[mi][ni][2]=v2; acc[mi][ni][3]=v3;
                    sA += v0 + v1; qA += v0*v0 + v1*v1;
                    sB += v2 + v3; qB += v2*v2 + v3*v3;
                }
#pragma unroll
                for (int o = 1; o <= 2; o <<= 1) {
                    sA += __shfl_xor_sync(0xffffffffu, sA, o);
                    qA += __shfl_xor_sync(0xffffffffu, qA, o);
                    sB += __shfl_xor_sync(0xffffffffu, sB, o);
                    qB += __shfl_xor_sync(0xffffffffu, qB, o);
                }
                if ((lane & 3) == 0) {
                    int rA = mi * 16 + rloc;
                    atomicAdd(&rowsum[rA], sA);   atomicAdd(&rowsq[rA], qA);
                    atomicAdd(&rowsum[rA+8], sB); atomicAdd(&rowsq[rA+8], qB);
                }
            }
            __syncthreads();
#pragma unroll
            for (int mi = 0; mi < 2; mi++) {
                int rA = mi * 16 + rloc;
                int rB = rA + 8;
                float mA = rowsum[rA] * (1.f/256.f);
                float rsA = rsqrtf(rowsq[rA] * (1.f/256.f) - mA*mA + LN_EPS);
                float mB = rowsum[rB] * (1.f/256.f);
                float rsB = rsqrtf(rowsq[rB] * (1.f/256.f) - mB*mB + LN_EPS);
#pragma unroll
                for (int ni = 0; ni < 4; ni++) {
                    int c0 = wn * 32 + ni * 8 + (lane & 3) * 2;
                    float g0=__ldg(lpg+c0), g1=__ldg(lpg+c0+1);
                    float o0f=__ldg(lpo+c0), o1f=__ldg(lpo+c0+1);
                    float u0 = (acc[mi][ni][0]-mA)*rsA*g0 + o0f;
                    float u1 = (acc[mi][ni][1]-mA)*rsA*g1 + o1f;
                    float u2 = (acc[mi][ni][2]-mB)*rsB*g0 + o0f;
                    float u3 = (acc[mi][ni][3]-mB)*rsB*g1 + o1f;
                    u0 = u0/(1.f+expf(-u0)); u1 = u1/(1.f+expf(-u1));
                    u2 = u2/(1.f+expf(-u2)); u3 = u3/(1.f+expf(-u3));
                    if (l < 3) {
                        int ck = c0 >> 6, cin = c0 & 63;
                        uint32_t wA = (uint32_t)(ck * 8192) + sw128((uint32_t)(rA * 128 + cin * 2));
                        uint32_t wB = (uint32_t)(ck * 8192) + sw128((uint32_t)(rB * 128 + cin * 2));
                        __nv_bfloat16 h0=__float2bfloat16(u0), h1=__float2bfloat16(u1);
                        __nv_bfloat16 l0=__float2bfloat16(u0-__bfloat162float(h0));
                        __nv_bfloat16 l1=__float2bfloat16(u1-__bfloat162float(h1));
                        __nv_bfloat16 h2=__float2bfloat16(u2), h3=__float2bfloat16(u3);
                        __nv_bfloat16 l2=__float2bfloat16(u2-__bfloat162float(h2));
                        __nv_bfloat16 l3=__float2bfloat16(u3-__bfloat162float(h3));
                        __nv_bfloat162 hh, ll;
                        hh.x=h0; hh.y=h1; ll.x=l0; ll.y=l1;
                        *(__nv_bfloat162*)(smem + HF_A + wA) = hh;
                        *(__nv_bfloat162*)(smem + HF_A + wA + 4096) = ll;
                        hh.x=h2; hh.y=h3; ll.x=l2; ll.y=l3;
                        *(__nv_bfloat162*)(smem + HF_A + wB) = hh;
                        *(__nv_bfloat162*)(smem + HF_A + wB + 4096) = ll;
                    } else {
                        store_hl2(Yhi, Ylo, (size_t)(row0 + rA), c0, u0, u1);
                        store_hl2(Yhi, Ylo, (size_t)(row0 + rB), c0, u2, u3);
                    }
                }
            }
            if (l < 3) {
                __syncthreads();
                if (tid < 32) { rowsum[tid] = 0.f; rowsq[tid] = 0.f; }
#pragma unroll
                for (int mi = 0; mi < 2; mi++)
#pragma unroll
                    for (int ni = 0; ni < 4; ni++)
#pragma unroll
                        for (int q = 0; q < 4; q++) acc[mi][ni][q] = 0.f;
                __syncthreads();
            }
        }
    }
}

// ---------------- merged weight prep ----------------
__global__ __launch_bounds__(256) void prep_all(
    const float* __restrict__ locw, const float* __restrict__ clsw,
    const float* __restrict__ boxw, __nv_bfloat16* __restrict__ whi,
    __nv_bfloat16* __restrict__ wlo,
    const float* __restrict__ lw3, const float* __restrict__ lw4,
    const float* __restrict__ lw5, __nv_bfloat16* __restrict__ lhi,
    __nv_bfloat16* __restrict__ llo)
{
    int blk = blockIdx.x;
    if (blk < 3072) {
        int mat = blk >> 8, o = blk & 255, k = threadIdx.x;
        const float* W = (mat < 4 ? locw : (mat < 8 ? clsw : boxw)) + (size_t)(mat & 3) * 65536;
        float v = W[k * 256 + o];
        __nv_bfloat16 h = __float2bfloat16(v);
        size_t oi = (size_t)mat * 65536 + (size_t)o * 256 + k;
        whi[oi] = h;
        wlo[oi] = __float2bfloat16(v - __bfloat162float(h));
    } else {
        int i = (blk - 3072) * 256 + threadIdx.x;
        float v = (i < 65536) ? lw3[i] : (i < 196608 ? lw4[i - 65536] : lw5[i - 196608]);
        __nv_bfloat16 h = __float2bfloat16(v);
        lhi[i] = h;
        llo[i] = __float2bfloat16(v - __bfloat162float(h));
    }
}

// ---------------- top-k ----------------
__global__ __launch_bounds__(512) void topk_kernel(
    const float* __restrict__ logits, float* __restrict__ vals, int* __restrict__ idxs)
{
    __shared__ float sv[NTOK];
    __shared__ float rv[16];
    __shared__ int   ri[16];
    __shared__ float wbv;
    __shared__ int   wbi;
    const int b = blockIdx.x, tid = threadIdx.x, lane = tid & 31, wd = tid >> 5;
    for (int i = tid; i < NTOK; i += 512) sv[i] = logits[b * NTOK + i];
    __syncthreads();

    float bv = -3.0e38f; int bi = tid;
    for (int i = tid; i < NTOK; i += 512) {
        float v = sv[i];
        if (v > bv) { bv = v; bi = i; }
    }

    for (int k = 0; k < KINST; k++) {
        float tv = bv; int ti = bi;
#pragma unroll
        for (int o = 16; o > 0; o >>= 1) {
            float ov = __shfl_xor_sync(0xffffffffu, tv, o);
            int   oi = __shfl_xor_sync(0xffffffffu, ti, o);
            if (ov > tv || (ov == tv && oi < ti)) { tv = ov; ti = oi; }
        }
        if (lane == 0) { rv[wd] = tv; ri[wd] = ti; }
        __syncthreads();
        if (wd == 0) {
            float xv = (lane < 16) ? rv[lane] : -3.3e38f;
            int   xi = (lane < 16) ? ri[lane] : 0;
#pragma unroll
            for (int o = 8; o > 0; o >>= 1) {
                float ov = __shfl_xor_sync(0xffffffffu, xv, o);
                int   oi = __shfl_xor_sync(0xffffffffu, xi, o);
                if (ov > xv || (ov == xv && oi < xi)) { xv = ov; xi = oi; }
            }
            if (lane == 0) {
                vals[b * KINST + k] = xv;
                idxs[b * KINST + k] = xi;
                wbv = xv; wbi = xi;
            }
        }
        __syncthreads();
        int win = wbi;
        if (bi == win) {
            sv[win] = -3.3e38f;
            bv = -3.0e38f; bi = tid;
            for (int i = tid; i < NTOK; i += 512) {
                float v = sv[i];
                if (v > bv) { bv = v; bi = i; }
            }
        }
    }
}

__device__ __forceinline__ float read_dim(const int* p) {
    int v = p[0];
    if (v > 0 && v < 1000000) return (float)v;
    return __int_as_float(v);
}

// ---------------- merged finals ----------------
__global__ __launch_bounds__(128) void finals_kernel(
    const __nv_bfloat16* __restrict__ chi, const __nv_bfloat16* __restrict__ clo,
    const __nv_bfloat16* __restrict__ bhi, const __nv_bfloat16* __restrict__ blo,
    const float* __restrict__ clsWf, const float* __restrict__ clsbf,
    const float* __restrict__ boxWf, const float* __restrict__ boxbf,
    const int* __restrict__ idxs, const int* __restrict__ p_fh,
    const int* __restrict__ p_fw, float* __restrict__ out)
{
    __shared__ float xc[256], xb[256], sval[80], e[4];
    int i = blockIdx.x, tid = threadIdx.x, lane = tid & 31, w = tid >> 5;
    {
        size_t base = (size_t)i * 256;
        xc[tid]     = __bfloat162float(chi[base+tid])     + __bfloat162float(clo[base+tid]);
        xc[tid+128] = __bfloat162float(chi[base+tid+128]) + __bfloat162float(clo[base+tid+128]);
        xb[tid]     = __bfloat162float(bhi[base+tid])     + __bfloat162float(blo[base+tid]);
        xb[tid+128] = __bfloat162float(bhi[base+tid+128]) + __bfloat162float(blo[base+tid+128]);
    }
    __syncthreads();
    float s = 0.f;
#pragma unroll
    for (int j = 0; j < 8; j++) {
        int k = lane + j * 32;
        s = fmaf(xb[k], boxWf[k * 4 + w], s);
    }
#pragma unroll
    for (int o = 16; o > 0; o >>= 1) s += __shfl_xor_sync(0xffffffffu, s, o);
    if (lane == 0) e[w] = expf(s + boxbf[w]);
    if (tid < 80) {
        float s2 = clsbf[tid];
        for (int k = 0; k < 256; k++) s2 = fmaf(xc[k], clsWf[k * 80 + tid], s2);
        sval[tid] = s2;
    }
    __syncthreads();
    if (tid == 0) {
        float bv = sval[0]; int bi = 0;
        for (int t = 1; t < 80; t++) if (sval[t] > bv) { bv = sval[t]; bi = t; }
        out[CL_OFF + i] = (float)bi;

        int n = idxs[i];
        int hsz, m;
        if (n < 4096)      { hsz = 64; m = n; }
        else if (n < 5120) { hsz = 32; m = n - 4096; }
        else               { hsz = 16; m = n - 5120; }
        int gy = m / hsz, gx = m % hsz;
        float inv = 1.0f / (float)hsz;
        float ox = (gx + 0.5f) * inv, oy = (gy + 0.5f) * inv;
        float half = 0.5f * inv;
        float fw = read_dim(p_fw), fh = read_dim(p_fh);
        float* o4 = out + BX_OFF + (size_t)i * 4;
        o4[0] = (ox - half * e[0]) * fw;
        o4[1] = (oy - half * e[1]) * fh;
        o4[2] = (ox + half * e[2]) * fw;
        o4[3] = (oy + half * e[3]) * fh;
    }
}

// ---------------- scores + num_instances ----------------
__global__ __launch_bounds__(800) void scores_kernel(
    const float* __restrict__ vals, float* __restrict__ out)
{
    __shared__ int cnt[BATCH];
    int tid = threadIdx.x;
    if (tid < BATCH) cnt[tid] = 0;
    __syncthreads();
    float v = vals[tid];
    out[SC_OFF + tid] = 1.f / (1.f + expf(-v));
    if (v > 0.f) atomicAdd(&cnt[tid / KINST], 1);
    __syncthreads();
    if (tid < BATCH) out[NI_OFF + tid] = (float)cnt[tid];
}

// ---------------- host launcher ----------------
extern "C" void kernel_launch(void* const* d_in, const int* in_sizes, int n_in,
                              void* d_out, int out_size)
{
    const float* x3     = (const float*)d_in[0];
    const float* x4     = (const float*)d_in[1];
    const float* x5     = (const float*)d_in[2];
    const float* lat_w3 = (const float*)d_in[3];
    const float* lat_w4 = (const float*)d_in[4];
    const float* lat_w5 = (const float*)d_in[5];
    const float* bn_g   = (const float*)d_in[6];
    const float* bn_b   = (const float*)d_in[7];
    const float* bn_m   = (const float*)d_in[8];
    const float* bn_v   = (const float*)d_in[9];
    const float* loc_Ws = (const float*)d_in[10];
    const float* loc_bs = (const float*)d_in[11];
    const float* loc_lng= (const float*)d_in[12];
    const float* loc_lnb= (const float*)d_in[13];
    const float* loc_Wf = (const float*)d_in[14];
    const float* loc_bf = (const float*)d_in[15];
    const float* cls_Ws = (const float*)d_in[16];
    const float* cls_bs = (const float*)d_in[17];
    const float* cls_lng= (const float*)d_in[18];
    const float* cls_lnb= (const float*)d_in[19];
    const float* cls_Wf = (const float*)d_in[20];
    const float* cls_bf = (const float*)d_in[21];
    const float* box_Ws = (const float*)d_in[22];
    const float* box_bs = (const float*)d_in[23];
    const float* box_lng= (const float*)d_in[24];
    const float* box_lnb= (const float*)d_in[25];
    const float* box_Wf = (const float*)d_in[26];
    const float* box_bf = (const float*)d_in[27];
    const int*   p_fh   = (const int*)d_in[28];
    const int*   p_fw   = (const int*)d_in[29];
    float* out = (float*)d_out;

    __nv_bfloat16 *flathi, *flatlo, *p0hi, *p0lo, *p1hi, *p1lo, *hd, *whi, *wlo, *lathi, *latlo;
    float *logits, *vals; int* idxp;
    cudaGetSymbolAddress((void**)&flathi, g_flathi);
    cudaGetSymbolAddress((void**)&flatlo, g_flatlo);
    cudaGetSymbolAddress((void**)&p0hi,   g_p0hi);
    cudaGetSymbolAddress((void**)&p0lo,   g_p0lo);
    cudaGetSymbolAddress((void**)&p1hi,   g_p1hi);
    cudaGetSymbolAddress((void**)&p1lo,   g_p1lo);
    cudaGetSymbolAddress((void**)&logits, g_logits);
    cudaGetSymbolAddress((void**)&vals,   g_vals);
    cudaGetSymbolAddress((void**)&idxp,   g_idx);
    cudaGetSymbolAddress((void**)&hd,     g_hd);
    cudaGetSymbolAddress((void**)&whi,    g_whi);
    cudaGetSymbolAddress((void**)&wlo,    g_wlo);
    cudaGetSymbolAddress((void**)&lathi,  g_lathi);
    cudaGetSymbolAddress((void**)&latlo,  g_latlo);

    const size_t HP = 896 * 256;
    __nv_bfloat16* c_hi = hd + 0*HP; __nv_bfloat16* c_lo = hd + 1*HP;
    __nv_bfloat16* b_hi = hd + 2*HP; __nv_bfloat16* b_lo = hd + 3*HP;

    cudaFuncSetAttribute(tc_gemm,     cudaFuncAttributeMaxDynamicSharedMemorySize, SMEM_TOTAL);
    cudaFuncSetAttribute(lat_gemm,    cudaFuncAttributeMaxDynamicSharedMemorySize, SMEM_TOTAL);
    cudaFuncSetAttribute(fused_heads, cudaFuncAttributeMaxDynamicSharedMemorySize, HF_SMEM);

    // 0) weight prep
    prep_all<<<4864, 256>>>(loc_Ws, cls_Ws, box_Ws, whi, wlo,
                            lat_w3, lat_w4, lat_w5, lathi, latlo);

    // 1) laterals
    {
        LatArgs L;
        L.x3 = x3; L.x4 = x4; L.x5 = x5;
        L.Whi = lathi; L.Wlo = latlo;
        L.bn_g = bn_g; L.bn_b = bn_b; L.bn_m = bn_m; L.bn_v = bn_v;
        L.Yhi = flathi; L.Ylo = flatlo;
        lat_gemm<<<1344, 256, SMEM_TOTAL>>>(L);
    }

    // 2) loc MLP: 4 layers, layer 4 fused with final dot -> logits
    {
        const __nv_bfloat16* curhi = flathi;
        const __nv_bfloat16* curlo = flatlo;
        __nv_bfloat16* phi[2] = { p0hi, p1hi };
        __nv_bfloat16* plo[2] = { p0lo, p1lo };
        for (int i = 0; i < 4; i++) {
            GArgs L; memset(&L, 0, sizeof(L));
            L.nrows = TOT;
            L.Ahi = curhi; L.Alo = curlo;
            L.Whi = whi + (size_t)i*65536; L.Wlo = wlo + (size_t)i*65536;
            L.pb = loc_bs + i*C; L.pg = loc_lng + i*C; L.po = loc_lnb + i*C;
            if (i == 3) { L.wf = loc_Wf; L.wfb = loc_bf; L.logits = logits; }
            else { L.Yhi = phi[i & 1]; L.Ylo = plo[i & 1]; }
            tc_gemm<<<TOT/32, 256, SMEM_TOTAL>>>(L);
            curhi = phi[i & 1]; curlo = plo[i & 1];
        }
    }

    // 3) top-k
    topk_kernel<<<BATCH, 512>>>(logits, vals, idxp);

    // 4) fused heads (one launch)
    {
        HArgs H;
        H.Ahi = flathi; H.Alo = flatlo;
        H.whi = whi; H.wlo = wlo;
        H.pb = cls_bs; H.pg = cls_lng; H.po = cls_lnb;
        H.pb2 = box_bs; H.pg2 = box_lng; H.po2 = box_lnb;
        H.Yhi = c_hi; H.Ylo = c_lo; H.Y2hi = b_hi; H.Y2lo = b_lo;
        H.idx = idxp;
        fused_heads<<<50, 256, HF_SMEM>>>(H);
    }

    // 5) finals + scores
    finals_kernel<<<800, 128>>>(c_hi, c_lo, b_hi, b_lo,
        cls_Wf, cls_bf, box_Wf, box_bf, idxp, p_fh, p_fw, out);
    scores_kernel<<<1, 800>>>(vals, out);
}